// round 15
// baseline (speedup 1.0000x reference)
#include <cuda_runtime.h>
#include <math.h>
#include <stdint.h>

// MultiStepUnitaryGCN collapses algebraically to a per-node MLP:
//   h   = relu(cos(sqrt(d)) * (x @ W1^T) + b1)
//   o   = cos(0.5*sqrt(d)) * (h @ W2^T) + b2
//   out = log_softmax(o, axis=1)
// (star-evolution weights [cos(t*sqrt(d)),0,...]; neighbors unused;
//  nbr_mask int32 [N,16]).
//
// R14 -> R15: occupancy play. 512thr/126regs was RF-full (no pipelining, no
// more warps; IPC 0.36). Now 1024 threads, 64 regs/thread (exactly fills the
// RF with 32 warps): warp tiles shrink to 32x16 (GEMM1) / 32x8 (GEMM2), so
// accumulators+fragments fit in 64 regs and the SMSPs get 8 warps each for
// latency coverage. Layout/math identical to R11 (AS=136 pair-packed
// conflict-free LDS.64).

#define N_NODES 50000
#define KNBR    16
#define CIN     128
#define CHID    128
#define COUT    64
#define TM      128
#define THREADS 1024
#define NTILES  391
#define GRID    148
#define AS      136      // packed tile row stride (words), ≡8 mod 32

// smem words:
//  sW1 17408 | sW2 8704 | sA 17408 | sC1 128 | sC2 128 | sB1 128 | sB2 64 |
//  sR1 1024 (row*8+wc max) | sR2 1024 (row*8+wc sum)
#define SMEM_WORDS (17408 + 8704 + 17408 + 128 + 128 + 128 + 64 + 1024 + 1024)
#define SMEM_BYTES (SMEM_WORDS * 4)

__device__ __forceinline__ uint32_t f2tf(float f) {
    uint32_t u; asm("cvt.rna.tf32.f32 %0, %1;" : "=r"(u) : "f"(f)); return u;
}

__device__ __forceinline__ void mma8(float* d, uint2 aP0, uint2 aP1, uint2 bP) {
    asm volatile(
        "mma.sync.aligned.m16n8k8.row.col.f32.tf32.tf32.f32 "
        "{%0,%1,%2,%3}, {%4,%5,%6,%7}, {%8,%9}, {%0,%1,%2,%3};"
        : "+f"(d[0]), "+f"(d[1]), "+f"(d[2]), "+f"(d[3])
        : "r"(aP0.x), "r"(aP1.x), "r"(aP0.y), "r"(aP1.y),
          "r"(bP.x), "r"(bP.y));
}

__global__ void __launch_bounds__(THREADS, 1)
gcn_mma_kernel(const float* __restrict__ x, const int* __restrict__ mask,
               const float* __restrict__ W1, const float* __restrict__ b1,
               const float* __restrict__ W2, const float* __restrict__ b2,
               float* __restrict__ out)
{
    extern __shared__ uint32_t smem[];
    uint32_t* sW1 = smem;                        // 17408
    uint32_t* sW2 = smem + 17408;                // 8704
    uint32_t* sA  = smem + 26112;                // 17408 (x, then h)
    float*    sC1 = (float*)(smem + 43520);      // 128
    float*    sC2 = sC1 + 128;
    float*    sB1 = sC2 + 128;
    float*    sB2 = sB1 + 128;                   // 64
    float*    sR1 = sB2 + 64;                    // 1024: per-row per-wc max
    float*    sR2 = sR1 + 1024;                  // 1024: per-row per-wc sum

    const int tid  = threadIdx.x;
    const int lane = tid & 31;
    const int warp = tid >> 5;                   // 0..31
    const int wr   = warp >> 3;                  // 0..3 row group (32 rows)
    const int wc   = warp & 7;                   // 0..7 col eighth
    const int m0   = wr * 32;
    const int lq   = lane >> 2;                  // 0..7
    const int lr   = lane & 3;                   // 0..3

    // ---- stage W1 packed (once, rna tf32)
    for (int idx = tid; idx < CHID * 16; idx += THREADS) {
        int c = idx >> 4, g = idx & 15;
        float4 v0 = *(const float4*)(W1 + c * CIN + g * 8);
        float4 v1 = *(const float4*)(W1 + c * CIN + g * 8 + 4);
        uint32_t* p = sW1 + c * AS + g * 8;
        *(uint2*)(p + 0) = make_uint2(f2tf(v0.x), f2tf(v1.x));
        *(uint2*)(p + 2) = make_uint2(f2tf(v0.y), f2tf(v1.y));
        *(uint2*)(p + 4) = make_uint2(f2tf(v0.z), f2tf(v1.z));
        *(uint2*)(p + 6) = make_uint2(f2tf(v0.w), f2tf(v1.w));
    }
    // ---- stage W2 packed (once, rna tf32)
    for (int idx = tid; idx < COUT * 16; idx += THREADS) {
        int c = idx >> 4, g = idx & 15;
        float4 v0 = *(const float4*)(W2 + c * CHID + g * 8);
        float4 v1 = *(const float4*)(W2 + c * CHID + g * 8 + 4);
        uint32_t* p = sW2 + c * AS + g * 8;
        *(uint2*)(p + 0) = make_uint2(f2tf(v0.x), f2tf(v1.x));
        *(uint2*)(p + 2) = make_uint2(f2tf(v0.y), f2tf(v1.y));
        *(uint2*)(p + 4) = make_uint2(f2tf(v0.z), f2tf(v1.z));
        *(uint2*)(p + 6) = make_uint2(f2tf(v0.w), f2tf(v1.w));
    }
    if (tid < CHID) sB1[tid] = b1[tid];
    if (tid < COUT) sB2[tid] = b2[tid];

    for (int tile = blockIdx.x; tile < NTILES; tile += GRID) {
        const int row0 = tile * TM;

        // ---- stage x tile packed (raw fp32 bits; tf32 truncation in HMMA)
        for (int idx = tid; idx < TM * 16; idx += THREADS) {
            int r = idx >> 4, g = idx & 15;
            float4 v0 = make_float4(0.f, 0.f, 0.f, 0.f), v1 = v0;
            if (row0 + r < N_NODES) {
                v0 = *(const float4*)(x + (size_t)(row0 + r) * CIN + g * 8);
                v1 = *(const float4*)(x + (size_t)(row0 + r) * CIN + g * 8 + 4);
            }
            uint32_t* p = sA + r * AS + g * 8;
            *(uint2*)(p + 0) = make_uint2(__float_as_uint(v0.x), __float_as_uint(v1.x));
            *(uint2*)(p + 2) = make_uint2(__float_as_uint(v0.y), __float_as_uint(v1.y));
            *(uint2*)(p + 4) = make_uint2(__float_as_uint(v0.z), __float_as_uint(v1.z));
            *(uint2*)(p + 6) = make_uint2(__float_as_uint(v0.w), __float_as_uint(v1.w));
        }
        // ---- per-tile cos factors
        if (tid < TM) {
            int r = row0 + tid;
            float c1 = 0.f, c2 = 0.f;
            if (r < N_NODES) {
                const int4* mp = (const int4*)(mask + (size_t)r * KNBR);
                int4 a = mp[0], b = mp[1], c = mp[2], d4 = mp[3];
                int d = a.x + a.y + a.z + a.w + b.x + b.y + b.z + b.w
                      + c.x + c.y + c.z + c.w + d4.x + d4.y + d4.z + d4.w;
                float sd = sqrtf((float)d);
                c1 = cosf(sd);
                c2 = cosf(0.5f * sd);
            }
            sC1[tid] = c1;
            sC2[tid] = c2;
        }
        __syncthreads();

        // ---- GEMM1: 128x128 = X @ W1^T ; warp tile 32x16 (nt 0..1)
        float d1[2][2][4];
#pragma unroll
        for (int mt = 0; mt < 2; ++mt)
#pragma unroll
            for (int nt = 0; nt < 2; ++nt)
#pragma unroll
                for (int j = 0; j < 4; ++j) d1[mt][nt][j] = 0.f;

#pragma unroll
        for (int g = 0; g < 16; ++g) {
            const int go = g * 8 + lr * 2;
            uint2 a0[2], a1[2];
#pragma unroll
            for (int mt = 0; mt < 2; ++mt) {
                int r = m0 + mt * 16 + lq;
                a0[mt] = *(const uint2*)(sA + r * AS + go);
                a1[mt] = *(const uint2*)(sA + (r + 8) * AS + go);
            }
#pragma unroll
            for (int nt = 0; nt < 2; ++nt) {
                int col = wc * 16 + nt * 8 + lq;
                uint2 bP = *(const uint2*)(sW1 + col * AS + go);
                mma8(d1[0][nt], a0[0], a1[0], bP);
                mma8(d1[1][nt], a0[1], a1[1], bP);
            }
        }
        __syncthreads();   // all warps done reading x from sA

        // ---- epilogue1: h = relu(c1*d + b1) -> sA packed (rna tf32)
#pragma unroll
        for (int mt = 0; mt < 2; ++mt) {
            int r = m0 + mt * 16 + lq;
            float c1a = sC1[r], c1b = sC1[r + 8];
#pragma unroll
            for (int nt = 0; nt < 2; ++nt) {
                int c = wc * 16 + nt * 8 + 2 * lr;
                float bx = sB1[c], by = sB1[c + 1];
                int g2 = wc * 2 + nt;
                int p0 = g2 * 8 + ((lr < 2) ? 4 * lr     : 4 * (lr - 2) + 1);
                int p1 = g2 * 8 + ((lr < 2) ? 4 * lr + 2 : 4 * (lr - 2) + 3);
                sA[r * AS + p0] = f2tf(fmaxf(fmaf(c1a, d1[mt][nt][0], bx), 0.f));
                sA[r * AS + p1] = f2tf(fmaxf(fmaf(c1a, d1[mt][nt][1], by), 0.f));
                sA[(r + 8) * AS + p0] = f2tf(fmaxf(fmaf(c1b, d1[mt][nt][2], bx), 0.f));
                sA[(r + 8) * AS + p1] = f2tf(fmaxf(fmaf(c1b, d1[mt][nt][3], by), 0.f));
            }
        }
        __syncthreads();

        // ---- GEMM2: 128x64 = H @ W2^T ; warp tile 32x8 (single n8 block)
        float d2[2][4];
#pragma unroll
        for (int mt = 0; mt < 2; ++mt)
#pragma unroll
            for (int j = 0; j < 4; ++j) d2[mt][j] = 0.f;

#pragma unroll
        for (int g = 0; g < 16; ++g) {
            const int go = g * 8 + lr * 2;
            uint2 a0[2], a1[2];
#pragma unroll
            for (int mt = 0; mt < 2; ++mt) {
                int r = m0 + mt * 16 + lq;
                a0[mt] = *(const uint2*)(sA + r * AS + go);
                a1[mt] = *(const uint2*)(sA + (r + 8) * AS + go);
            }
            int col = wc * 8 + lq;
            uint2 bP = *(const uint2*)(sW2 + col * AS + go);
            mma8(d2[0], a0[0], a1[0], bP);
            mma8(d2[1], a0[1], a1[1], bP);
        }

        // ---- epilogue2: o = c2*d + b2 (regs) ; row-max partials -> sR1
        float o[2][4];
        float rmax[2][2];
#pragma unroll
        for (int mt = 0; mt < 2; ++mt) {
            int r = m0 + mt * 16 + lq;
            float c2a = sC2[r], c2b = sC2[r + 8];
            int c = wc * 8 + 2 * lr;
            float bx = sB2[c], by = sB2[c + 1];
            o[mt][0] = fmaf(c2a, d2[mt][0], bx);
            o[mt][1] = fmaf(c2a, d2[mt][1], by);
            o[mt][2] = fmaf(c2b, d2[mt][2], bx);
            o[mt][3] = fmaf(c2b, d2[mt][3], by);
            rmax[mt][0] = fmaxf(o[mt][0], o[mt][1]);
            rmax[mt][1] = fmaxf(o[mt][2], o[mt][3]);
        }
#pragma unroll
        for (int mt = 0; mt < 2; ++mt)
#pragma unroll
            for (int i = 0; i < 2; ++i) {
                float m = rmax[mt][i];
                m = fmaxf(m, __shfl_xor_sync(0xffffffffu, m, 1));
                m = fmaxf(m, __shfl_xor_sync(0xffffffffu, m, 2));
                int r = m0 + mt * 16 + i * 8 + lq;
                sR1[r * 8 + wc] = m;
            }
        __syncthreads();   // sR1 ready; sA reads drained

        float gmax[2][2], psum[2][2];
#pragma unroll
        for (int mt = 0; mt < 2; ++mt)
#pragma unroll
            for (int i = 0; i < 2; ++i) {
                int r = m0 + mt * 16 + i * 8 + lq;
                const float4 m0v = *(const float4*)(sR1 + r * 8);
                const float4 m1v = *(const float4*)(sR1 + r * 8 + 4);
                float m = fmaxf(fmaxf(m0v.x, m0v.y), fmaxf(m0v.z, m0v.w));
                m = fmaxf(m, fmaxf(fmaxf(m1v.x, m1v.y), fmaxf(m1v.z, m1v.w)));
                gmax[mt][i] = m;
            }
#pragma unroll
        for (int mt = 0; mt < 2; ++mt) {
            psum[mt][0] = expf(o[mt][0] - gmax[mt][0]) + expf(o[mt][1] - gmax[mt][0]);
            psum[mt][1] = expf(o[mt][2] - gmax[mt][1]) + expf(o[mt][3] - gmax[mt][1]);
        }
#pragma unroll
        for (int mt = 0; mt < 2; ++mt)
#pragma unroll
            for (int i = 0; i < 2; ++i) {
                float s = psum[mt][i];
                s += __shfl_xor_sync(0xffffffffu, s, 1);
                s += __shfl_xor_sync(0xffffffffu, s, 2);
                int r = m0 + mt * 16 + i * 8 + lq;
                sR2[r * 8 + wc] = s;
            }
        __syncthreads();

        // ---- lse + store
#pragma unroll
        for (int mt = 0; mt < 2; ++mt)
#pragma unroll
            for (int i = 0; i < 2; ++i) {
                int r = m0 + mt * 16 + i * 8 + lq;
                int grow = row0 + r;
                const float4 s0v = *(const float4*)(sR2 + r * 8);
                const float4 s1v = *(const float4*)(sR2 + r * 8 + 4);
                float s = (s0v.x + s0v.y) + (s0v.z + s0v.w)
                        + (s1v.x + s1v.y) + (s1v.z + s1v.w);
                float lse = gmax[mt][i] + logf(s);
                if (grow < N_NODES) {
                    float* dst = out + (size_t)grow * COUT + wc * 8 + 2 * lr;
                    *(float2*)dst = make_float2(o[mt][2 * i] - lse,
                                                o[mt][2 * i + 1] - lse);
                }
            }
        __syncthreads();   // sR2/sA reads drained before next-tile staging
    }
}

extern "C" void kernel_launch(void* const* d_in, const int* in_sizes, int n_in,
                              void* d_out, int out_size)
{
    const float* x    = (const float*)d_in[0];
    // d_in[1] = neighbors (unused)
    const int*   mask = (const int*)d_in[2];
    const float* W1   = (const float*)d_in[3];
    const float* b1   = (const float*)d_in[4];
    const float* W2   = (const float*)d_in[5];
    const float* b2   = (const float*)d_in[6];
    float*       out  = (float*)d_out;

    cudaFuncSetAttribute(gcn_mma_kernel,
                         cudaFuncAttributeMaxDynamicSharedMemorySize, SMEM_BYTES);

    gcn_mma_kernel<<<GRID, THREADS, SMEM_BYTES>>>(x, mask, W1, b1, W2, b2, out);
}

// round 16
// speedup vs baseline: 1.4551x; 1.4551x over previous
#include <cuda_runtime.h>
#include <math.h>
#include <stdint.h>

// MultiStepUnitaryGCN collapses algebraically to a per-node MLP:
//   h   = relu(cos(sqrt(d)) * (x @ W1^T) + b1)
//   o   = cos(0.5*sqrt(d)) * (h @ W2^T) + b2
//   out = log_softmax(o, axis=1)
// (star-evolution weights [cos(t*sqrt(d)),0,...]; neighbors unused;
//  nbr_mask int32 [N,16]).
//
// R15 -> R16: revert to R11 structure (512 thr, 32x32/32x16 warp tiles —
// the traffic/occupancy sweet spot), switch tf32 m16n8k8 -> bf16 m16n8k16:
// halves MMA count, halves A+B LDS bytes AND instructions. Same pair-packed
// conflict-free layout, words are bf16x2, AS=72 (≡8 mod 32). Precision
// budget: bf16-rn eps ~1.1e-3 rms -> predicted output rel_err ~3e-4 (<1e-3).

#define N_NODES 50000
#define KNBR    16
#define CIN     128
#define CHID    128
#define COUT    64
#define TM      128
#define THREADS 512
#define NTILES  391
#define GRID    148
#define AS      72       // packed tile row stride (words of bf16x2), ≡8 mod 32

// per row: 8 k-groups (16 k each) of 8 bf16x2 words; pair (word j, word j+4)
// stored as uint2 at g*8 + j*2  -> fragment fetch = one LDS.64, banks
// lq*8+lr*2: perfect 32-bank tiling per 16-lane phase (zero conflicts).

// smem words:
//  sW1 128*72=9216 | sW2 64*72=4608 | sA 128*72=9216 |
//  sC1 128 | sC2 128 | sB1 128 | sB2 64 | sR1 512 | sR2 512
#define SMEM_WORDS (9216 + 4608 + 9216 + 128 + 128 + 128 + 64 + 512 + 512)
#define SMEM_BYTES (SMEM_WORDS * 4)

__device__ __forceinline__ uint32_t bfpack(float lo, float hi) {
    // bf16x2 word: low half = lo (even k), high half = hi (odd k)
    uint32_t u;
    asm("cvt.rn.bf16x2.f32 %0, %1, %2;" : "=r"(u) : "f"(hi), "f"(lo));
    return u;
}

__device__ __forceinline__ void mma16(float* d, uint2 aP0, uint2 aP1, uint2 bP) {
    asm volatile(
        "mma.sync.aligned.m16n8k16.row.col.f32.bf16.bf16.f32 "
        "{%0,%1,%2,%3}, {%4,%5,%6,%7}, {%8,%9}, {%0,%1,%2,%3};"
        : "+f"(d[0]), "+f"(d[1]), "+f"(d[2]), "+f"(d[3])
        : "r"(aP0.x), "r"(aP1.x), "r"(aP0.y), "r"(aP1.y),
          "r"(bP.x), "r"(bP.y));
}

__global__ void __launch_bounds__(THREADS, 1)
gcn_mma_kernel(const float* __restrict__ x, const int* __restrict__ mask,
               const float* __restrict__ W1, const float* __restrict__ b1,
               const float* __restrict__ W2, const float* __restrict__ b2,
               float* __restrict__ out)
{
    extern __shared__ uint32_t smem[];
    uint32_t* sW1 = smem;                        // 9216
    uint32_t* sW2 = smem + 9216;                 // 4608
    uint32_t* sA  = smem + 13824;                // 9216 (x, then h)
    float*    sC1 = (float*)(smem + 23040);
    float*    sC2 = sC1 + 128;
    float*    sB1 = sC2 + 128;
    float*    sB2 = sB1 + 128;
    float*    sR1 = sB2 + 64;                    // 512: per-row per-wc max
    float*    sR2 = sR1 + 512;                   // 512: per-row per-wc sum

    const int tid  = threadIdx.x;
    const int lane = tid & 31;
    const int warp = tid >> 5;
    const int wr   = warp >> 2;                  // 0..3 row group
    const int wc   = warp & 3;                   // 0..3 col quarter
    const int m0   = wr * 32;
    const int lq   = lane >> 2;                  // 0..7
    const int lr   = lane & 3;                   // 0..3

    // ---- stage W1 packed bf16 (once): c = output col, g = 16k-group
    for (int idx = tid; idx < CHID * 8; idx += THREADS) {
        int c = idx >> 3, g = idx & 7;
        const float* wp = W1 + c * CIN + g * 16;
        float4 v0 = *(const float4*)(wp);
        float4 v1 = *(const float4*)(wp + 4);
        float4 v2 = *(const float4*)(wp + 8);
        float4 v3 = *(const float4*)(wp + 12);
        uint32_t w0 = bfpack(v0.x, v0.y), w1 = bfpack(v0.z, v0.w);
        uint32_t w2 = bfpack(v1.x, v1.y), w3 = bfpack(v1.z, v1.w);
        uint32_t w4 = bfpack(v2.x, v2.y), w5 = bfpack(v2.z, v2.w);
        uint32_t w6 = bfpack(v3.x, v3.y), w7 = bfpack(v3.z, v3.w);
        uint4* p = (uint4*)(sW1 + c * AS + g * 8);
        p[0] = make_uint4(w0, w4, w1, w5);
        p[1] = make_uint4(w2, w6, w3, w7);
    }
    // ---- stage W2 packed bf16 (once)
    for (int idx = tid; idx < COUT * 8; idx += THREADS) {
        int c = idx >> 3, g = idx & 7;
        const float* wp = W2 + c * CHID + g * 16;
        float4 v0 = *(const float4*)(wp);
        float4 v1 = *(const float4*)(wp + 4);
        float4 v2 = *(const float4*)(wp + 8);
        float4 v3 = *(const float4*)(wp + 12);
        uint32_t w0 = bfpack(v0.x, v0.y), w1 = bfpack(v0.z, v0.w);
        uint32_t w2 = bfpack(v1.x, v1.y), w3 = bfpack(v1.z, v1.w);
        uint32_t w4 = bfpack(v2.x, v2.y), w5 = bfpack(v2.z, v2.w);
        uint32_t w6 = bfpack(v3.x, v3.y), w7 = bfpack(v3.z, v3.w);
        uint4* p = (uint4*)(sW2 + c * AS + g * 8);
        p[0] = make_uint4(w0, w4, w1, w5);
        p[1] = make_uint4(w2, w6, w3, w7);
    }
    if (tid < CHID) sB1[tid] = b1[tid];
    if (tid < COUT) sB2[tid] = b2[tid];

    for (int tile = blockIdx.x; tile < NTILES; tile += GRID) {
        const int row0 = tile * TM;

        // ---- stage x tile packed bf16 (coalesced float4 reads)
        for (int idx = tid; idx < TM * 8; idx += THREADS) {
            int r = idx >> 3, g = idx & 7;
            float4 v0 = make_float4(0.f, 0.f, 0.f, 0.f), v1 = v0, v2 = v0, v3 = v0;
            if (row0 + r < N_NODES) {
                const float* xp = x + (size_t)(row0 + r) * CIN + g * 16;
                v0 = *(const float4*)(xp);
                v1 = *(const float4*)(xp + 4);
                v2 = *(const float4*)(xp + 8);
                v3 = *(const float4*)(xp + 12);
            }
            uint32_t w0 = bfpack(v0.x, v0.y), w1 = bfpack(v0.z, v0.w);
            uint32_t w2 = bfpack(v1.x, v1.y), w3 = bfpack(v1.z, v1.w);
            uint32_t w4 = bfpack(v2.x, v2.y), w5 = bfpack(v2.z, v2.w);
            uint32_t w6 = bfpack(v3.x, v3.y), w7 = bfpack(v3.z, v3.w);
            uint4* p = (uint4*)(sA + r * AS + g * 8);
            p[0] = make_uint4(w0, w4, w1, w5);
            p[1] = make_uint4(w2, w6, w3, w7);
        }
        // ---- per-tile cos factors
        if (tid < TM) {
            int r = row0 + tid;
            float c1 = 0.f, c2 = 0.f;
            if (r < N_NODES) {
                const int4* mp = (const int4*)(mask + (size_t)r * KNBR);
                int4 a = mp[0], b = mp[1], c = mp[2], d4 = mp[3];
                int d = a.x + a.y + a.z + a.w + b.x + b.y + b.z + b.w
                      + c.x + c.y + c.z + c.w + d4.x + d4.y + d4.z + d4.w;
                float sd = sqrtf((float)d);
                c1 = cosf(sd);
                c2 = cosf(0.5f * sd);
            }
            sC1[tid] = c1;
            sC2[tid] = c2;
        }
        __syncthreads();

        // ---- GEMM1: 128x128 = X @ W1^T ; warp tile 32x32 ; 8 k16-steps
        float d1[2][4][4];
#pragma unroll
        for (int mt = 0; mt < 2; ++mt)
#pragma unroll
            for (int nt = 0; nt < 4; ++nt)
#pragma unroll
                for (int j = 0; j < 4; ++j) d1[mt][nt][j] = 0.f;

#pragma unroll
        for (int g = 0; g < 8; ++g) {
            const int go = g * 8 + lr * 2;
            uint2 a0[2], a1[2];
#pragma unroll
            for (int mt = 0; mt < 2; ++mt) {
                int r = m0 + mt * 16 + lq;
                a0[mt] = *(const uint2*)(sA + r * AS + go);
                a1[mt] = *(const uint2*)(sA + (r + 8) * AS + go);
            }
#pragma unroll
            for (int nt = 0; nt < 4; ++nt) {
                int col = wc * 32 + nt * 8 + lq;
                uint2 bP = *(const uint2*)(sW1 + col * AS + go);
                mma16(d1[0][nt], a0[0], a1[0], bP);
                mma16(d1[1][nt], a0[1], a1[1], bP);
            }
        }
        __syncthreads();   // all warps done reading x from sA

        // ---- epilogue1: h = relu(c1*d + b1) -> sA packed bf16x2
        // cols (c, c+1) -> one bf16x2 word w = wc*16 + nt*4 + lr
        // packed off: g2 = wc*2+(nt>>1); nt even: g2*8+lr*2 ; nt odd: +1
#pragma unroll
        for (int mt = 0; mt < 2; ++mt) {
            int r = m0 + mt * 16 + lq;
            float c1a = sC1[r], c1b = sC1[r + 8];
#pragma unroll
            for (int nt = 0; nt < 4; ++nt) {
                int c = wc * 32 + nt * 8 + 2 * lr;
                float bx = sB1[c], by = sB1[c + 1];
                int off = (wc * 2 + (nt >> 1)) * 8 + lr * 2 + (nt & 1);
                float h0 = fmaxf(fmaf(c1a, d1[mt][nt][0], bx), 0.f);
                float h1 = fmaxf(fmaf(c1a, d1[mt][nt][1], by), 0.f);
                float h2 = fmaxf(fmaf(c1b, d1[mt][nt][2], bx), 0.f);
                float h3 = fmaxf(fmaf(c1b, d1[mt][nt][3], by), 0.f);
                sA[r * AS + off]       = bfpack(h0, h1);
                sA[(r + 8) * AS + off] = bfpack(h2, h3);
            }
        }
        __syncthreads();

        // ---- GEMM2: 128x64 = H @ W2^T ; warp tile 32x16 ; 8 k16-steps
        float d2[2][2][4];
#pragma unroll
        for (int mt = 0; mt < 2; ++mt)
#pragma unroll
            for (int nt = 0; nt < 2; ++nt)
#pragma unroll
                for (int j = 0; j < 4; ++j) d2[mt][nt][j] = 0.f;

#pragma unroll
        for (int g = 0; g < 8; ++g) {
            const int go = g * 8 + lr * 2;
            uint2 a0[2], a1[2];
#pragma unroll
            for (int mt = 0; mt < 2; ++mt) {
                int r = m0 + mt * 16 + lq;
                a0[mt] = *(const uint2*)(sA + r * AS + go);
                a1[mt] = *(const uint2*)(sA + (r + 8) * AS + go);
            }
#pragma unroll
            for (int nt = 0; nt < 2; ++nt) {
                int col = wc * 16 + nt * 8 + lq;
                uint2 bP = *(const uint2*)(sW2 + col * AS + go);
                mma16(d2[0][nt], a0[0], a1[0], bP);
                mma16(d2[1][nt], a0[1], a1[1], bP);
            }
        }

        // ---- epilogue2: o = c2*d + b2 (regs) ; row-max partials -> sR1
        float o[2][2][4];
        float rmax[2][2] = {{-1e30f, -1e30f}, {-1e30f, -1e30f}};
#pragma unroll
        for (int mt = 0; mt < 2; ++mt) {
            int r = m0 + mt * 16 + lq;
            float c2a = sC2[r], c2b = sC2[r + 8];
#pragma unroll
            for (int nt = 0; nt < 2; ++nt) {
                int c = wc * 16 + nt * 8 + 2 * lr;
                float bx = sB2[c], by = sB2[c + 1];
                o[mt][nt][0] = fmaf(c2a, d2[mt][nt][0], bx);
                o[mt][nt][1] = fmaf(c2a, d2[mt][nt][1], by);
                o[mt][nt][2] = fmaf(c2b, d2[mt][nt][2], bx);
                o[mt][nt][3] = fmaf(c2b, d2[mt][nt][3], by);
                rmax[mt][0] = fmaxf(rmax[mt][0], fmaxf(o[mt][nt][0], o[mt][nt][1]));
                rmax[mt][1] = fmaxf(rmax[mt][1], fmaxf(o[mt][nt][2], o[mt][nt][3]));
            }
        }
#pragma unroll
        for (int mt = 0; mt < 2; ++mt)
#pragma unroll
            for (int i = 0; i < 2; ++i) {
                float m = rmax[mt][i];
                m = fmaxf(m, __shfl_xor_sync(0xffffffffu, m, 1));
                m = fmaxf(m, __shfl_xor_sync(0xffffffffu, m, 2));
                int r = m0 + mt * 16 + i * 8 + lq;
                sR1[r * 4 + wc] = m;
            }
        __syncthreads();

        float gmax[2][2], psum[2][2];
#pragma unroll
        for (int mt = 0; mt < 2; ++mt)
#pragma unroll
            for (int i = 0; i < 2; ++i) {
                int r = m0 + mt * 16 + i * 8 + lq;
                const float4 mv = *(const float4*)(sR1 + r * 4);
                gmax[mt][i] = fmaxf(fmaxf(mv.x, mv.y), fmaxf(mv.z, mv.w));
            }
#pragma unroll
        for (int mt = 0; mt < 2; ++mt) {
            float s0 = 0.f, s1 = 0.f;
#pragma unroll
            for (int nt = 0; nt < 2; ++nt) {
                s0 += expf(o[mt][nt][0] - gmax[mt][0]);
                s0 += expf(o[mt][nt][1] - gmax[mt][0]);
                s1 += expf(o[mt][nt][2] - gmax[mt][1]);
                s1 += expf(o[mt][nt][3] - gmax[mt][1]);
            }
            psum[mt][0] = s0;
            psum[mt][1] = s1;
        }
#pragma unroll
        for (int mt = 0; mt < 2; ++mt)
#pragma unroll
            for (int i = 0; i < 2; ++i) {
                float s = psum[mt][i];
                s += __shfl_xor_sync(0xffffffffu, s, 1);
                s += __shfl_xor_sync(0xffffffffu, s, 2);
                int r = m0 + mt * 16 + i * 8 + lq;
                sR2[r * 4 + wc] = s;
            }
        __syncthreads();

        // ---- lse + store
#pragma unroll
        for (int mt = 0; mt < 2; ++mt)
#pragma unroll
            for (int i = 0; i < 2; ++i) {
                int r = m0 + mt * 16 + i * 8 + lq;
                int grow = row0 + r;
                const float4 sv = *(const float4*)(sR2 + r * 4);
                float lse = gmax[mt][i] + logf(sv.x + sv.y + sv.z + sv.w);
                if (grow < N_NODES) {
                    float* dst = out + (size_t)grow * COUT + wc * 16 + 2 * lr;
#pragma unroll
                    for (int nt = 0; nt < 2; ++nt) {
                        float v0 = o[mt][nt][2 * i]     - lse;
                        float v1 = o[mt][nt][2 * i + 1] - lse;
                        *(float2*)(dst + nt * 8) = make_float2(v0, v1);
                    }
                }
            }
        __syncthreads();   // sR2/sA reads drained before next-tile staging
    }
}

extern "C" void kernel_launch(void* const* d_in, const int* in_sizes, int n_in,
                              void* d_out, int out_size)
{
    const float* x    = (const float*)d_in[0];
    // d_in[1] = neighbors (unused)
    const int*   mask = (const int*)d_in[2];
    const float* W1   = (const float*)d_in[3];
    const float* b1   = (const float*)d_in[4];
    const float* W2   = (const float*)d_in[5];
    const float* b2   = (const float*)d_in[6];
    float*       out  = (float*)d_out;

    cudaFuncSetAttribute(gcn_mma_kernel,
                         cudaFuncAttributeMaxDynamicSharedMemorySize, SMEM_BYTES);

    gcn_mma_kernel<<<GRID, THREADS, SMEM_BYTES>>>(x, mask, W1, b1, W2, b2, out);
}

// round 17
// speedup vs baseline: 1.5563x; 1.0695x over previous
#include <cuda_runtime.h>
#include <math.h>
#include <stdint.h>

// MultiStepUnitaryGCN collapses algebraically to a per-node MLP:
//   h   = relu(cos(sqrt(d)) * (x @ W1^T) + b1)
//   o   = cos(0.5*sqrt(d)) * (h @ W2^T) + b2
//   out = log_softmax(o, axis=1)
// (star-evolution weights [cos(t*sqrt(d)),0,...]; neighbors unused;
//  nbr_mask int32 [N,16]).
//
// R16 -> R17: occupancy at FIXED warp-tile. 768 threads / 24 warps
// (6 row-groups x 4 col-quarters), TM=192: every warp runs the exact R16
// inner loops (32x32 / 32x16 bf16 m16n8k16, AS=72 pair-packed conflict-free
// LDS.64). launch_bounds caps regs at 85 (no spill per reg budget).
// Softmax uses __expf/__logf (MUFU) to trim scalar instructions.

#define N_NODES 50000
#define KNBR    16
#define CIN     128
#define CHID    128
#define COUT    64
#define TM      192
#define THREADS 768
#define NTILES  261      // ceil(50000/192)
#define GRID    148
#define AS      72       // packed tile row stride (bf16x2 words), ≡8 mod 32

// smem words:
//  sW1 128*72=9216 | sW2 64*72=4608 | sA 192*72=13824 |
//  sC1 192 | sC2 192 | sB1 128 | sB2 64 | sR1 768 | sR2 768
#define SMEM_WORDS (9216 + 4608 + 13824 + 192 + 192 + 128 + 64 + 768 + 768)
#define SMEM_BYTES (SMEM_WORDS * 4)

__device__ __forceinline__ uint32_t bfpack(float lo, float hi) {
    uint32_t u;
    asm("cvt.rn.bf16x2.f32 %0, %1, %2;" : "=r"(u) : "f"(hi), "f"(lo));
    return u;
}

__device__ __forceinline__ void mma16(float* d, uint2 aP0, uint2 aP1, uint2 bP) {
    asm volatile(
        "mma.sync.aligned.m16n8k16.row.col.f32.bf16.bf16.f32 "
        "{%0,%1,%2,%3}, {%4,%5,%6,%7}, {%8,%9}, {%0,%1,%2,%3};"
        : "+f"(d[0]), "+f"(d[1]), "+f"(d[2]), "+f"(d[3])
        : "r"(aP0.x), "r"(aP1.x), "r"(aP0.y), "r"(aP1.y),
          "r"(bP.x), "r"(bP.y));
}

__global__ void __launch_bounds__(THREADS, 1)
gcn_mma_kernel(const float* __restrict__ x, const int* __restrict__ mask,
               const float* __restrict__ W1, const float* __restrict__ b1,
               const float* __restrict__ W2, const float* __restrict__ b2,
               float* __restrict__ out)
{
    extern __shared__ uint32_t smem[];
    uint32_t* sW1 = smem;                        // 9216
    uint32_t* sW2 = smem + 9216;                 // 4608
    uint32_t* sA  = smem + 13824;                // 13824 (x, then h)
    float*    sC1 = (float*)(smem + 27648);      // 192
    float*    sC2 = sC1 + 192;
    float*    sB1 = sC2 + 192;                   // 128
    float*    sB2 = sB1 + 128;                   // 64
    float*    sR1 = sB2 + 64;                    // 768: per-row per-wc max
    float*    sR2 = sR1 + 768;                   // 768: per-row per-wc sum

    const int tid  = threadIdx.x;
    const int lane = tid & 31;
    const int warp = tid >> 5;                   // 0..23
    const int wr   = warp >> 2;                  // 0..5 row group (32 rows)
    const int wc   = warp & 3;                   // 0..3 col quarter
    const int m0   = wr * 32;
    const int lq   = lane >> 2;                  // 0..7
    const int lr   = lane & 3;                   // 0..3

    // ---- stage W1 packed bf16 (once)
    for (int idx = tid; idx < CHID * 8; idx += THREADS) {
        int c = idx >> 3, g = idx & 7;
        const float* wp = W1 + c * CIN + g * 16;
        float4 v0 = *(const float4*)(wp);
        float4 v1 = *(const float4*)(wp + 4);
        float4 v2 = *(const float4*)(wp + 8);
        float4 v3 = *(const float4*)(wp + 12);
        uint32_t w0 = bfpack(v0.x, v0.y), w1 = bfpack(v0.z, v0.w);
        uint32_t w2 = bfpack(v1.x, v1.y), w3 = bfpack(v1.z, v1.w);
        uint32_t w4 = bfpack(v2.x, v2.y), w5 = bfpack(v2.z, v2.w);
        uint32_t w6 = bfpack(v3.x, v3.y), w7 = bfpack(v3.z, v3.w);
        uint4* p = (uint4*)(sW1 + c * AS + g * 8);
        p[0] = make_uint4(w0, w4, w1, w5);
        p[1] = make_uint4(w2, w6, w3, w7);
    }
    // ---- stage W2 packed bf16 (once)
    for (int idx = tid; idx < COUT * 8; idx += THREADS) {
        int c = idx >> 3, g = idx & 7;
        const float* wp = W2 + c * CHID + g * 16;
        float4 v0 = *(const float4*)(wp);
        float4 v1 = *(const float4*)(wp + 4);
        float4 v2 = *(const float4*)(wp + 8);
        float4 v3 = *(const float4*)(wp + 12);
        uint32_t w0 = bfpack(v0.x, v0.y), w1 = bfpack(v0.z, v0.w);
        uint32_t w2 = bfpack(v1.x, v1.y), w3 = bfpack(v1.z, v1.w);
        uint32_t w4 = bfpack(v2.x, v2.y), w5 = bfpack(v2.z, v2.w);
        uint32_t w6 = bfpack(v3.x, v3.y), w7 = bfpack(v3.z, v3.w);
        uint4* p = (uint4*)(sW2 + c * AS + g * 8);
        p[0] = make_uint4(w0, w4, w1, w5);
        p[1] = make_uint4(w2, w6, w3, w7);
    }
    if (tid < CHID) sB1[tid] = b1[tid];
    if (tid < COUT) sB2[tid] = b2[tid];

    for (int tile = blockIdx.x; tile < NTILES; tile += GRID) {
        const int row0 = tile * TM;

        // ---- stage x tile packed bf16 (coalesced float4 reads)
        for (int idx = tid; idx < TM * 8; idx += THREADS) {
            int r = idx >> 3, g = idx & 7;
            float4 v0 = make_float4(0.f, 0.f, 0.f, 0.f), v1 = v0, v2 = v0, v3 = v0;
            if (row0 + r < N_NODES) {
                const float* xp = x + (size_t)(row0 + r) * CIN + g * 16;
                v0 = *(const float4*)(xp);
                v1 = *(const float4*)(xp + 4);
                v2 = *(const float4*)(xp + 8);
                v3 = *(const float4*)(xp + 12);
            }
            uint32_t w0 = bfpack(v0.x, v0.y), w1 = bfpack(v0.z, v0.w);
            uint32_t w2 = bfpack(v1.x, v1.y), w3 = bfpack(v1.z, v1.w);
            uint32_t w4 = bfpack(v2.x, v2.y), w5 = bfpack(v2.z, v2.w);
            uint32_t w6 = bfpack(v3.x, v3.y), w7 = bfpack(v3.z, v3.w);
            uint4* p = (uint4*)(sA + r * AS + g * 8);
            p[0] = make_uint4(w0, w4, w1, w5);
            p[1] = make_uint4(w2, w6, w3, w7);
        }
        // ---- per-tile cos factors
        if (tid < TM) {
            int r = row0 + tid;
            float c1 = 0.f, c2 = 0.f;
            if (r < N_NODES) {
                const int4* mp = (const int4*)(mask + (size_t)r * KNBR);
                int4 a = mp[0], b = mp[1], c = mp[2], d4 = mp[3];
                int d = a.x + a.y + a.z + a.w + b.x + b.y + b.z + b.w
                      + c.x + c.y + c.z + c.w + d4.x + d4.y + d4.z + d4.w;
                float sd = sqrtf((float)d);
                c1 = cosf(sd);
                c2 = cosf(0.5f * sd);
            }
            sC1[tid] = c1;
            sC2[tid] = c2;
        }
        __syncthreads();

        // ---- GEMM1: 192x128 = X @ W1^T ; warp tile 32x32 ; 8 k16-steps
        float d1[2][4][4];
#pragma unroll
        for (int mt = 0; mt < 2; ++mt)
#pragma unroll
            for (int nt = 0; nt < 4; ++nt)
#pragma unroll
                for (int j = 0; j < 4; ++j) d1[mt][nt][j] = 0.f;

#pragma unroll
        for (int g = 0; g < 8; ++g) {
            const int go = g * 8 + lr * 2;
            uint2 a0[2], a1[2];
#pragma unroll
            for (int mt = 0; mt < 2; ++mt) {
                int r = m0 + mt * 16 + lq;
                a0[mt] = *(const uint2*)(sA + r * AS + go);
                a1[mt] = *(const uint2*)(sA + (r + 8) * AS + go);
            }
#pragma unroll
            for (int nt = 0; nt < 4; ++nt) {
                int col = wc * 32 + nt * 8 + lq;
                uint2 bP = *(const uint2*)(sW1 + col * AS + go);
                mma16(d1[0][nt], a0[0], a1[0], bP);
                mma16(d1[1][nt], a0[1], a1[1], bP);
            }
        }
        __syncthreads();   // all warps done reading x from sA

        // ---- epilogue1: h = relu(c1*d + b1) -> sA packed bf16x2
#pragma unroll
        for (int mt = 0; mt < 2; ++mt) {
            int r = m0 + mt * 16 + lq;
            float c1a = sC1[r], c1b = sC1[r + 8];
#pragma unroll
            for (int nt = 0; nt < 4; ++nt) {
                int c = wc * 32 + nt * 8 + 2 * lr;
                float bx = sB1[c], by = sB1[c + 1];
                int off = (wc * 2 + (nt >> 1)) * 8 + lr * 2 + (nt & 1);
                float h0 = fmaxf(fmaf(c1a, d1[mt][nt][0], bx), 0.f);
                float h1 = fmaxf(fmaf(c1a, d1[mt][nt][1], by), 0.f);
                float h2 = fmaxf(fmaf(c1b, d1[mt][nt][2], bx), 0.f);
                float h3 = fmaxf(fmaf(c1b, d1[mt][nt][3], by), 0.f);
                sA[r * AS + off]       = bfpack(h0, h1);
                sA[(r + 8) * AS + off] = bfpack(h2, h3);
            }
        }
        __syncthreads();

        // ---- GEMM2: 192x64 = H @ W2^T ; warp tile 32x16 ; 8 k16-steps
        float d2[2][2][4];
#pragma unroll
        for (int mt = 0; mt < 2; ++mt)
#pragma unroll
            for (int nt = 0; nt < 2; ++nt)
#pragma unroll
                for (int j = 0; j < 4; ++j) d2[mt][nt][j] = 0.f;

#pragma unroll
        for (int g = 0; g < 8; ++g) {
            const int go = g * 8 + lr * 2;
            uint2 a0[2], a1[2];
#pragma unroll
            for (int mt = 0; mt < 2; ++mt) {
                int r = m0 + mt * 16 + lq;
                a0[mt] = *(const uint2*)(sA + r * AS + go);
                a1[mt] = *(const uint2*)(sA + (r + 8) * AS + go);
            }
#pragma unroll
            for (int nt = 0; nt < 2; ++nt) {
                int col = wc * 16 + nt * 8 + lq;
                uint2 bP = *(const uint2*)(sW2 + col * AS + go);
                mma16(d2[0][nt], a0[0], a1[0], bP);
                mma16(d2[1][nt], a0[1], a1[1], bP);
            }
        }

        // ---- epilogue2: o = c2*d + b2 (regs) ; row-max partials -> sR1
        float o[2][2][4];
        float rmax[2][2] = {{-1e30f, -1e30f}, {-1e30f, -1e30f}};
#pragma unroll
        for (int mt = 0; mt < 2; ++mt) {
            int r = m0 + mt * 16 + lq;
            float c2a = sC2[r], c2b = sC2[r + 8];
#pragma unroll
            for (int nt = 0; nt < 2; ++nt) {
                int c = wc * 16 + nt * 8 + 2 * lr;
                float bx = sB2[c], by = sB2[c + 1];
                o[mt][nt][0] = fmaf(c2a, d2[mt][nt][0], bx);
                o[mt][nt][1] = fmaf(c2a, d2[mt][nt][1], by);
                o[mt][nt][2] = fmaf(c2b, d2[mt][nt][2], bx);
                o[mt][nt][3] = fmaf(c2b, d2[mt][nt][3], by);
                rmax[mt][0] = fmaxf(rmax[mt][0], fmaxf(o[mt][nt][0], o[mt][nt][1]));
                rmax[mt][1] = fmaxf(rmax[mt][1], fmaxf(o[mt][nt][2], o[mt][nt][3]));
            }
        }
#pragma unroll
        for (int mt = 0; mt < 2; ++mt)
#pragma unroll
            for (int i = 0; i < 2; ++i) {
                float m = rmax[mt][i];
                m = fmaxf(m, __shfl_xor_sync(0xffffffffu, m, 1));
                m = fmaxf(m, __shfl_xor_sync(0xffffffffu, m, 2));
                int r = m0 + mt * 16 + i * 8 + lq;
                sR1[r * 4 + wc] = m;
            }
        __syncthreads();

        float gmax[2][2], psum[2][2];
#pragma unroll
        for (int mt = 0; mt < 2; ++mt)
#pragma unroll
            for (int i = 0; i < 2; ++i) {
                int r = m0 + mt * 16 + i * 8 + lq;
                const float4 mv = *(const float4*)(sR1 + r * 4);
                gmax[mt][i] = fmaxf(fmaxf(mv.x, mv.y), fmaxf(mv.z, mv.w));
            }
#pragma unroll
        for (int mt = 0; mt < 2; ++mt) {
            float s0 = 0.f, s1 = 0.f;
#pragma unroll
            for (int nt = 0; nt < 2; ++nt) {
                s0 += __expf(o[mt][nt][0] - gmax[mt][0]);
                s0 += __expf(o[mt][nt][1] - gmax[mt][0]);
                s1 += __expf(o[mt][nt][2] - gmax[mt][1]);
                s1 += __expf(o[mt][nt][3] - gmax[mt][1]);
            }
            psum[mt][0] = s0;
            psum[mt][1] = s1;
        }
#pragma unroll
        for (int mt = 0; mt < 2; ++mt)
#pragma unroll
            for (int i = 0; i < 2; ++i) {
                float s = psum[mt][i];
                s += __shfl_xor_sync(0xffffffffu, s, 1);
                s += __shfl_xor_sync(0xffffffffu, s, 2);
                int r = m0 + mt * 16 + i * 8 + lq;
                sR2[r * 4 + wc] = s;
            }
        __syncthreads();

        // ---- lse + store
#pragma unroll
        for (int mt = 0; mt < 2; ++mt)
#pragma unroll
            for (int i = 0; i < 2; ++i) {
                int r = m0 + mt * 16 + i * 8 + lq;
                int grow = row0 + r;
                const float4 sv = *(const float4*)(sR2 + r * 4);
                float lse = gmax[mt][i] + __logf(sv.x + sv.y + sv.z + sv.w);
                if (grow < N_NODES) {
                    float* dst = out + (size_t)grow * COUT + wc * 16 + 2 * lr;
#pragma unroll
                    for (int nt = 0; nt < 2; ++nt) {
                        float v0 = o[mt][nt][2 * i]     - lse;
                        float v1 = o[mt][nt][2 * i + 1] - lse;
                        *(float2*)(dst + nt * 8) = make_float2(v0, v1);
                    }
                }
            }
        __syncthreads();   // sR2/sA reads drained before next-tile staging
    }
}

extern "C" void kernel_launch(void* const* d_in, const int* in_sizes, int n_in,
                              void* d_out, int out_size)
{
    const float* x    = (const float*)d_in[0];
    // d_in[1] = neighbors (unused)
    const int*   mask = (const int*)d_in[2];
    const float* W1   = (const float*)d_in[3];
    const float* b1   = (const float*)d_in[4];
    const float* W2   = (const float*)d_in[5];
    const float* b2   = (const float*)d_in[6];
    float*       out  = (float*)d_out;

    cudaFuncSetAttribute(gcn_mma_kernel,
                         cudaFuncAttributeMaxDynamicSharedMemorySize, SMEM_BYTES);

    gcn_mma_kernel<<<GRID, THREADS, SMEM_BYTES>>>(x, mask, W1, b1, W2, b2, out);
}